// round 8
// baseline (speedup 1.0000x reference)
#include <cuda_runtime.h>
#include <cstdint>

#define N_AGENTS 11
#define OBS_DIM 115
#define GS_DIM (N_AGENTS * OBS_DIM)   // 1265
#define ID_LO 97
#define FULL 0xFFFFFFFFu
#define WPB 8                          // warps per block; 4 rows per warp

__device__ __forceinline__ void cp_async4(uint32_t dst, const float* src) {
    asm volatile("cp.async.ca.shared.global [%0], [%1], 4;" :: "r"(dst), "l"(src));
}
#define CP_COMMIT() asm volatile("cp.async.commit_group;" ::: "memory")
#define CP_WAIT(n)  asm volatile("cp.async.wait_group %0;" :: "n"(n) : "memory")

// Finish one row-pair: route pos, per-agent math, argmin, softmax, write.
__device__ __forceinline__ void finish_pair(
    float posv0, float posv1,            // gathered pos values (22 lanes)
    float bx, float by, float tm,        // this half's row scalars
    float qa, int sub, int halfw,
    float* __restrict__ out, long long row0, long long row1)
{
    const float POS_INF = __int_as_float(0x7f800000);
    const float NEG_INF = __int_as_float(0xff800000);

    const float pxA = __shfl_sync(FULL, posv0, 2 * sub);
    const float pyA = __shfl_sync(FULL, posv0, 2 * sub + 1);
    const float pxB = __shfl_sync(FULL, posv1, 2 * sub);
    const float pyB = __shfl_sync(FULL, posv1, 2 * sub + 1);
    const float px = halfw ? pxB : pxA;
    const float py = halfw ? pyB : pyA;

    const float dxg = bx - 1.0f;
    const float bgd = sqrtf(dxg * dxg + by * by);
    const bool valid = (tm != 0.0f) && (bgd > 0.19f) && (bgd < 0.99f);

    float dist = POS_INF, gd = 0.0f;
    int aidx = 64;
    if (sub < N_AGENTS) {
        const float dxb = px - bx, dyb = py - by;
        dist = sqrtf(dxb * dxb + dyb * dyb);
        const float dxgl = px - 1.0f;
        gd = sqrtf(dxgl * dxgl + py * py);
        aidx = sub;
    }

    // half-warp argmin, first-index tie-break (jnp.argmin)
    float mval = dist; int midx = aidx;
    #pragma unroll
    for (int off = 8; off > 0; off >>= 1) {
        const float ov = __shfl_xor_sync(FULL, mval, off);
        const int   oi = __shfl_xor_sync(FULL, midx, off);
        if (ov < mval || (ov == mval && oi < midx)) { mval = ov; midx = oi; }
    }

    float combined = NEG_INF;
    if (sub < N_AGENTS) {
        if (valid) combined = (aidx == midx) ? 5.0f : 0.0f;
        else       combined = 1.0f / (gd + 1e-6f);
    }

    float m = combined;
    #pragma unroll
    for (int off = 8; off > 0; off >>= 1)
        m = fmaxf(m, __shfl_xor_sync(FULL, m, off));

    const float e = (sub < N_AGENTS) ? expf(combined - m) : 0.0f;

    float s = e, qe = qa * e;
    #pragma unroll
    for (int off = 8; off > 0; off >>= 1) {
        s  += __shfl_xor_sync(FULL, s,  off);
        qe += __shfl_xor_sync(FULL, qe, off);
    }

    if (sub == 0)
        out[halfw ? row1 : row0] = (qe / s) * (float)N_AGENTS;
}

__global__ __launch_bounds__(256, 5)
void qllmmixer_kernel(const float* __restrict__ q,        // [B, 11]
                      const float* __restrict__ gs,       // [B, 1265]
                      float* __restrict__ out,            // [B]
                      int B)
{
    // [warp][pair][row-in-pair][elem] id-window tiles
    __shared__ float tile[WPB][2][2][128];

    const int wb    = threadIdx.x >> 5;
    const int lane  = threadIdx.x & 31;
    const int halfw = lane >> 4;
    const int sub   = lane & 15;

    const long long base = ((long long)blockIdx.x * WPB + wb) * 4;
    if (base >= B) return;               // B multiple of 32 -> all 4 rows valid

    const float* g[4];
    g[0] = gs + base * GS_DIM;
    g[1] = g[0] + GS_DIM;
    g[2] = g[1] + GS_DIM;
    g[3] = g[2] + GS_DIM;

    // ---- Issue all 4 rows' id-window tiles via cp.async (2 commit groups).
    #pragma unroll
    for (int p = 0; p < 2; ++p) {
        #pragma unroll
        for (int i = 0; i < 8; ++i) {
            const int t = lane + 32 * i;          // 0..255
            const int r = t >> 7;                 // row within pair
            const int u = t & 127;
            if (u < N_AGENTS * N_AGENTS) {
                const int a = u / N_AGENTS;
                const int k = u - a * N_AGENTS;
                const uint32_t dst =
                    (uint32_t)__cvta_generic_to_shared(&tile[wb][p][r][u]);
                cp_async4(dst, g[2 * p + r] + a * OBS_DIM + ID_LO + k);
            }
        }
        CP_COMMIT();
    }

    // ---- Independent loads (overlap the cp.asyncs): scalars + q rows.
    const float* gA = g[halfw];          // pair0 row for this half
    const float* gB = g[2 + halfw];      // pair1 row for this half
    const float bxA = __ldg(gA + 88), byA = __ldg(gA + 89), tmA = __ldg(gA + 95);
    const float bxB = __ldg(gB + 88), byB = __ldg(gB + 89), tmB = __ldg(gB + 95);

    float qaA = 0.0f, qaB = 0.0f;
    if (sub < N_AGENTS) {
        qaA = __ldg(q + (base + halfw) * N_AGENTS + sub);
        qaB = __ldg(q + (base + 2 + halfw) * N_AGENTS + sub);
    }

    const int pa   = lane >> 1;          // agent for pos gather
    const int half = lane & 1;

    // ---- Pair 0: wait tiles, argmax, issue pos gather.
    CP_WAIT(1);
    __syncwarp();

    int bidP0 = 0;
    if (sub < N_AGENTS) {
        const float* tp = &tile[wb][0][halfw][sub * N_AGENTS];
        float best = tp[0];
        #pragma unroll
        for (int k = 1; k < N_AGENTS; ++k)
            if (tp[k] > best) { best = tp[k]; bidP0 = k; }   // first-max
    }
    const int b00 = __shfl_sync(FULL, bidP0, pa);        // row base+0
    const int b01 = __shfl_sync(FULL, bidP0, 16 + pa);   // row base+1
    float pv00 = 0.0f, pv01 = 0.0f;
    if (lane < 2 * N_AGENTS) {
        pv00 = __ldcs(g[0] + pa * OBS_DIM + 2 * b00 + half);
        pv01 = __ldcs(g[1] + pa * OBS_DIM + 2 * b01 + half);
    }

    // ---- Pair 1: wait tiles, argmax, issue pos gather (pair0 loads age in flight).
    CP_WAIT(0);
    __syncwarp();

    int bidP1 = 0;
    if (sub < N_AGENTS) {
        const float* tp = &tile[wb][1][halfw][sub * N_AGENTS];
        float best = tp[0];
        #pragma unroll
        for (int k = 1; k < N_AGENTS; ++k)
            if (tp[k] > best) { best = tp[k]; bidP1 = k; }
    }
    const int b10 = __shfl_sync(FULL, bidP1, pa);        // row base+2
    const int b11 = __shfl_sync(FULL, bidP1, 16 + pa);   // row base+3
    float pv10 = 0.0f, pv11 = 0.0f;
    if (lane < 2 * N_AGENTS) {
        pv10 = __ldcs(g[2] + pa * OBS_DIM + 2 * b10 + half);
        pv11 = __ldcs(g[3] + pa * OBS_DIM + 2 * b11 + half);
    }

    // ---- Finish both pairs (pair0's pos loads have had pair1's phase to land).
    finish_pair(pv00, pv01, bxA, byA, tmA, qaA, sub, halfw, out, base,     base + 1);
    finish_pair(pv10, pv11, bxB, byB, tmB, qaB, sub, halfw, out, base + 2, base + 3);
}

extern "C" void kernel_launch(void* const* d_in, const int* in_sizes, int n_in,
                              void* d_out, int out_size)
{
    const float* q  = (const float*)d_in[0];   // agents_q  [128,512,11]
    const float* gs = (const float*)d_in[1];   // global_state [128,512,1265]
    float* out = (float*)d_out;

    const int B = in_sizes[0] / N_AGENTS;      // 65536 rows

    const int rows_per_block = WPB * 4;        // 32
    const int blocks = (B + rows_per_block - 1) / rows_per_block;

    qllmmixer_kernel<<<blocks, 32 * WPB>>>(q, gs, out, B);
}

// round 9
// speedup vs baseline: 1.0148x; 1.0148x over previous
#include <cuda_runtime.h>
#include <cstdint>

#define N_AGENTS 11
#define OBS_DIM 115
#define GS_DIM (N_AGENTS * OBS_DIM)   // 1265
#define ID_LO 97
#define FULL 0xFFFFFFFFu
#define WPB 8                          // warps per block; 4 rows per warp

// Finish one row-pair: route pos, per-agent math, argmin, softmax, write.
__device__ __forceinline__ void finish_pair(
    float posv0, float posv1,            // gathered pos values (22 lanes)
    float bx, float by, float tm,        // this half's row scalars
    float qa, int sub, int halfw,
    float* __restrict__ out, long long row0, long long row1)
{
    const float POS_INF = __int_as_float(0x7f800000);
    const float NEG_INF = __int_as_float(0xff800000);

    const float pxA = __shfl_sync(FULL, posv0, 2 * sub);
    const float pyA = __shfl_sync(FULL, posv0, 2 * sub + 1);
    const float pxB = __shfl_sync(FULL, posv1, 2 * sub);
    const float pyB = __shfl_sync(FULL, posv1, 2 * sub + 1);
    const float px = halfw ? pxB : pxA;
    const float py = halfw ? pyB : pyA;

    const float dxg = bx - 1.0f;
    const float bgd = sqrtf(dxg * dxg + by * by);
    const bool valid = (tm != 0.0f) && (bgd > 0.19f) && (bgd < 0.99f);

    float dist = POS_INF, gd = 0.0f;
    int aidx = 64;
    if (sub < N_AGENTS) {
        const float dxb = px - bx, dyb = py - by;
        dist = sqrtf(dxb * dxb + dyb * dyb);
        const float dxgl = px - 1.0f;
        gd = sqrtf(dxgl * dxgl + py * py);
        aidx = sub;
    }

    // half-warp argmin, first-index tie-break (jnp.argmin)
    float mval = dist; int midx = aidx;
    #pragma unroll
    for (int off = 8; off > 0; off >>= 1) {
        const float ov = __shfl_xor_sync(FULL, mval, off);
        const int   oi = __shfl_xor_sync(FULL, midx, off);
        if (ov < mval || (ov == mval && oi < midx)) { mval = ov; midx = oi; }
    }

    float combined = NEG_INF;
    if (sub < N_AGENTS) {
        if (valid) combined = (aidx == midx) ? 5.0f : 0.0f;
        else       combined = 1.0f / (gd + 1e-6f);
    }

    float m = combined;
    #pragma unroll
    for (int off = 8; off > 0; off >>= 1)
        m = fmaxf(m, __shfl_xor_sync(FULL, m, off));

    const float e = (sub < N_AGENTS) ? expf(combined - m) : 0.0f;

    float s = e, qe = qa * e;
    #pragma unroll
    for (int off = 8; off > 0; off >>= 1) {
        s  += __shfl_xor_sync(FULL, s,  off);
        qe += __shfl_xor_sync(FULL, qe, off);
    }

    if (sub == 0)
        out[halfw ? row1 : row0] = (qe / s) * (float)N_AGENTS;
}

__global__ __launch_bounds__(256, 6)
void qllmmixer_kernel(const float* __restrict__ q,        // [B, 11]
                      const float* __restrict__ gs,       // [B, 1265]
                      float* __restrict__ out,            // [B]
                      int B)
{
    // [warp][pair][row-in-pair][elem] id-window tiles
    __shared__ float tile[WPB][2][2][128];

    const int wb    = threadIdx.x >> 5;
    const int lane  = threadIdx.x & 31;
    const int halfw = lane >> 4;
    const int sub   = lane & 15;

    const long long base = ((long long)blockIdx.x * WPB + wb) * 4;
    if (base >= B) return;               // B multiple of 32 -> all 4 rows valid

    const float* g0 = gs + base * GS_DIM;
    const float* g1 = g0 + GS_DIM;
    const float* g2 = g1 + GS_DIM;
    const float* g3 = g2 + GS_DIM;

    // ---- Issue all 4 rows' id-window tiles: 16 predicated LDG->STS.
    // ptxas front-batches the LDGs; all lines in flight before any consumer.
    #pragma unroll
    for (int p = 0; p < 2; ++p) {
        const float* ga = p ? g2 : g0;
        const float* gb = p ? g3 : g1;
        #pragma unroll
        for (int i = 0; i < 8; ++i) {
            const int t = lane + 32 * i;          // 0..255
            const int r = t >> 7;                 // row within pair
            const int u = t & 127;
            if (u < N_AGENTS * N_AGENTS) {
                const int a = u / N_AGENTS;
                const int k = u - a * N_AGENTS;
                tile[wb][p][r][u] = __ldcs((r ? gb : ga) + a * OBS_DIM + ID_LO + k);
            }
        }
    }

    // ---- Independent loads overlap the tile fills: scalars + q rows.
    const float* gA = halfw ? g1 : g0;   // pair0 row for this half
    const float* gB = halfw ? g3 : g2;   // pair1 row for this half
    const float bxA = __ldg(gA + 88), byA = __ldg(gA + 89), tmA = __ldg(gA + 95);
    const float bxB = __ldg(gB + 88), byB = __ldg(gB + 89), tmB = __ldg(gB + 95);

    float qaA = 0.0f, qaB = 0.0f;
    if (sub < N_AGENTS) {
        qaA = __ldg(q + (base + halfw) * N_AGENTS + sub);
        qaB = __ldg(q + (base + 2 + halfw) * N_AGENTS + sub);
    }

    __syncwarp();

    const int pa   = lane >> 1;          // agent for pos gather
    const int half = lane & 1;

    // ---- Pair 0: argmax, issue pos gather.
    int bidP0 = 0;
    if (sub < N_AGENTS) {
        const float* tp = &tile[wb][0][halfw][sub * N_AGENTS];
        float best = tp[0];
        #pragma unroll
        for (int k = 1; k < N_AGENTS; ++k)
            if (tp[k] > best) { best = tp[k]; bidP0 = k; }   // first-max
    }
    const int b00 = __shfl_sync(FULL, bidP0, pa);        // row base+0
    const int b01 = __shfl_sync(FULL, bidP0, 16 + pa);   // row base+1
    float pv00 = 0.0f, pv01 = 0.0f;
    if (lane < 2 * N_AGENTS) {
        pv00 = __ldcs(g0 + pa * OBS_DIM + 2 * b00 + half);
        pv01 = __ldcs(g1 + pa * OBS_DIM + 2 * b01 + half);
    }

    // ---- Pair 1: argmax (overlaps pair0 pos flight), issue pos gather.
    int bidP1 = 0;
    if (sub < N_AGENTS) {
        const float* tp = &tile[wb][1][halfw][sub * N_AGENTS];
        float best = tp[0];
        #pragma unroll
        for (int k = 1; k < N_AGENTS; ++k)
            if (tp[k] > best) { best = tp[k]; bidP1 = k; }
    }
    const int b10 = __shfl_sync(FULL, bidP1, pa);        // row base+2
    const int b11 = __shfl_sync(FULL, bidP1, 16 + pa);   // row base+3
    float pv10 = 0.0f, pv11 = 0.0f;
    if (lane < 2 * N_AGENTS) {
        pv10 = __ldcs(g2 + pa * OBS_DIM + 2 * b10 + half);
        pv11 = __ldcs(g3 + pa * OBS_DIM + 2 * b11 + half);
    }

    // ---- Finish both pairs (pair0's pos loads aged during pair1's argmax).
    finish_pair(pv00, pv01, bxA, byA, tmA, qaA, sub, halfw, out, base,     base + 1);
    finish_pair(pv10, pv11, bxB, byB, tmB, qaB, sub, halfw, out, base + 2, base + 3);
}

extern "C" void kernel_launch(void* const* d_in, const int* in_sizes, int n_in,
                              void* d_out, int out_size)
{
    const float* q  = (const float*)d_in[0];   // agents_q  [128,512,11]
    const float* gs = (const float*)d_in[1];   // global_state [128,512,1265]
    float* out = (float*)d_out;

    const int B = in_sizes[0] / N_AGENTS;      // 65536 rows

    const int rows_per_block = WPB * 4;        // 32
    const int blocks = (B + rows_per_block - 1) / rows_per_block;

    qllmmixer_kernel<<<blocks, 32 * WPB>>>(q, gs, out, B);
}

// round 10
// speedup vs baseline: 1.0846x; 1.0687x over previous
#include <cuda_runtime.h>

#define N_AGENTS 11
#define OBS_DIM 115
#define GS_DIM (N_AGENTS * OBS_DIM)   // 1265
#define ID_LO 97
#define FULL 0xFFFFFFFFu
#define WPB 4                          // warps per block; 2 rows per warp

__global__ __launch_bounds__(128, 16)
void qllmmixer_kernel(const float* __restrict__ q,        // [B, 11]
                      const float* __restrict__ gs,       // [B, 1265]
                      float* __restrict__ out,            // [B]
                      int B)
{
    // Two 121-float id-window tiles per warp (rows r0, r1).
    __shared__ float tile[WPB][2][128];

    const int wb    = threadIdx.x >> 5;
    const int lane  = threadIdx.x & 31;
    const int halfw = lane >> 4;        // which of the 2 rows this half-warp reduces
    const int sub   = lane & 15;

    const long long r0 = ((long long)blockIdx.x * WPB + wb) * 2;
    const long long r1 = r0 + 1;
    if (r0 >= B) return;                // B is a multiple of 8 -> r1 valid too

    const float POS_INF = __int_as_float(0x7f800000);
    const float NEG_INF = __int_as_float(0xff800000);

    const float* grow0 = gs + r0 * GS_DIM;
    const float* grow1 = gs + r1 * GS_DIM;

    // ---- Issue the big-latency loads FIRST: both rows' id-window tiles.
    // 8 independent LDGs, coalesced within each 44B window (~5 lines each).
    #pragma unroll
    for (int i = 0; i < 8; ++i) {
        const int t = lane + 32 * i;          // 0..255
        const int r = t >> 7;                 // 0: row0, 1: row1
        const int u = t & 127;
        if (u < N_AGENTS * N_AGENTS) {
            const int a = u / N_AGENTS;
            const int k = u - a * N_AGENTS;
            const float* g = r ? grow1 : grow0;
            tile[wb][r][u] = __ldcs(g + a * OBS_DIM + ID_LO + k);
        }
    }

    // ---- Fill the latency shadow with the independent small loads.
    const float bx0 = __ldg(grow0 + 88), by0 = __ldg(grow0 + 89), tm0 = __ldg(grow0 + 95);
    const float bx1 = __ldg(grow1 + 88), by1 = __ldg(grow1 + 89), tm1 = __ldg(grow1 + 95);

    float qa = 0.0f;
    if (sub < N_AGENTS)
        qa = __ldg(q + (halfw ? r1 : r0) * N_AGENTS + sub);

    __syncwarp();

    // ---- Per-agent argmax: row0 on lanes 0..10, row1 on lanes 16..26 (parallel).
    int bid = 0;
    if (sub < N_AGENTS) {
        const float* tp = &tile[wb][halfw][sub * N_AGENTS];
        float best = tp[0];
        #pragma unroll
        for (int k = 1; k < N_AGENTS; ++k) {
            const float v = tp[k];
            if (v > best) { best = v; bid = k; }   // strict '>' = first-max
        }
    }

    // ---- Dependent pos gathers: both rows issued back-to-back.
    const int pa   = lane >> 1;                          // agent 0..15
    const int half = lane & 1;
    const int bid0 = __shfl_sync(FULL, bid, pa);         // row0 bids on lanes 0..10
    const int bid1 = __shfl_sync(FULL, bid, 16 + pa);    // row1 bids on lanes 16..26
    float posv0 = 0.0f, posv1 = 0.0f;
    if (lane < 2 * N_AGENTS) {
        posv0 = __ldcs(grow0 + pa * OBS_DIM + 2 * bid0 + half);
        posv1 = __ldcs(grow1 + pa * OBS_DIM + 2 * bid1 + half);
    }

    // Route (px, py) of agent `sub` of this half's row to this lane.
    const float pxA = __shfl_sync(FULL, posv0, 2 * sub);
    const float pyA = __shfl_sync(FULL, posv0, 2 * sub + 1);
    const float pxB = __shfl_sync(FULL, posv1, 2 * sub);
    const float pyB = __shfl_sync(FULL, posv1, 2 * sub + 1);
    const float px = halfw ? pxB : pxA;
    const float py = halfw ? pyB : pyA;

    // Per-half row scalars
    const float bx = halfw ? bx1 : bx0;
    const float by = halfw ? by1 : by0;
    const float tm = halfw ? tm1 : tm0;
    const float dxg = bx - 1.0f;
    const float bgd = sqrtf(dxg * dxg + by * by);
    const bool valid = (tm != 0.0f) && (bgd > 0.19f) && (bgd < 0.99f);

    // ---- Per-agent math
    float dist = POS_INF;
    float gd   = 0.0f;
    int   aidx = 64;
    if (sub < N_AGENTS) {
        const float dxb = px - bx;
        const float dyb = py - by;
        dist = sqrtf(dxb * dxb + dyb * dyb);
        const float dxgl = px - 1.0f;
        gd = sqrtf(dxgl * dxgl + py * py);
        aidx = sub;
    }

    // ---- half-warp argmin (first-index tie-break, jnp.argmin)
    float mval = dist;
    int   midx = aidx;
    #pragma unroll
    for (int off = 8; off > 0; off >>= 1) {
        const float ov = __shfl_xor_sync(FULL, mval, off);
        const int   oi = __shfl_xor_sync(FULL, midx, off);
        if (ov < mval || (ov == mval && oi < midx)) { mval = ov; midx = oi; }
    }

    // ---- combined + half-warp softmax
    float combined = NEG_INF;
    if (sub < N_AGENTS) {
        if (valid) combined = (aidx == midx) ? 5.0f : 0.0f;
        else       combined = 1.0f / (gd + 1e-6f);
    }

    float m = combined;
    #pragma unroll
    for (int off = 8; off > 0; off >>= 1)
        m = fmaxf(m, __shfl_xor_sync(FULL, m, off));

    const float e = (sub < N_AGENTS) ? expf(combined - m) : 0.0f;

    float s  = e;
    float qe = qa * e;
    #pragma unroll
    for (int off = 8; off > 0; off >>= 1) {
        s  += __shfl_xor_sync(FULL, s,  off);
        qe += __shfl_xor_sync(FULL, qe, off);
    }

    if (sub == 0)
        out[halfw ? r1 : r0] = (qe / s) * (float)N_AGENTS;
}

extern "C" void kernel_launch(void* const* d_in, const int* in_sizes, int n_in,
                              void* d_out, int out_size)
{
    const float* q  = (const float*)d_in[0];   // agents_q  [128,512,11]
    const float* gs = (const float*)d_in[1];   // global_state [128,512,1265]
    float* out = (float*)d_out;

    const int B = in_sizes[0] / N_AGENTS;      // 65536 rows

    const int rows_per_block = WPB * 2;        // 8
    const int blocks = (B + rows_per_block - 1) / rows_per_block;

    qllmmixer_kernel<<<blocks, 32 * WPB>>>(q, gs, out, B);
}